// round 15
// baseline (speedup 1.0000x reference)
#include <cuda_runtime.h>
#include <cuda_bf16.h>
#include <math.h>
#include <stdint.h>

#define B_SZ   4096
#define C_DIM  1024
#define N_DIM  256
#define M_DIM  64
#define G_COLS 198
#define HALF_B (B_SZ / 2)

// ---------------------------------------------------------------------------
// device scratch
// ---------------------------------------------------------------------------
__device__ float g_G[B_SZ * G_COLS];                 // gate pre-activations

__device__ __forceinline__ float softplus_f(float x) {
    return (x > 20.f) ? x : log1pf(expf(x));
}
__device__ __forceinline__ float sigmoid_f(float x) {
    return 1.f / (1.f + expf(-x));
}
__device__ __forceinline__ uint32_t bf2u(__nv_bfloat162 v) {
    return *reinterpret_cast<uint32_t*>(&v);
}

// row c of the concatenated weight matrix [198, 1024]
__device__ __forceinline__ const float* wrow_ptr(
    int c, const float* Wk, const float* Wb, const float* Wg,
    const float* Ws, const float* Wgm, const float* We, const float* Wa)
{
    if (c < 64)   return Wk + (size_t)c * C_DIM;
    if (c == 64)  return Wb;
    if (c == 65)  return Wg;
    if (c < 69)   return Ws + (size_t)(c - 66) * C_DIM;
    if (c == 69)  return Wgm;
    if (c < 134)  return We + (size_t)(c - 70) * C_DIM;
    if (c < 198)  return Wa + (size_t)(c - 134) * C_DIM;
    return nullptr;
}
__device__ __forceinline__ float bias_val(
    int c, const float* bk, const float* bb, const float* bg,
    const float* bs, const float* bgm, const float* be, const float* ba)
{
    if (c < 64)   return bk[c];
    if (c == 64)  return bb[0];
    if (c == 65)  return bg[0];
    if (c < 69)   return bs[c - 66];
    if (c == 69)  return bgm[0];
    if (c < 134)  return be[c - 70];
    if (c < 198)  return ba[c - 134];
    return 0.f;
}

// ---------------------------------------------------------------------------
// Kernel 1: HMMA bf16-split GEMM  G[rowOff:rowOff+2048, 198] = emb @ Wcat.T + b
// Folded W conversion; CTA tile 64x128, 8 warps; grid (32,2) per half.
// K-chunk 32 fp32: {Ahi*Bhi + Ahi*Blo + Alo*Bhi}.
// 2-stage SMEM double buffer, register-prefetch G2R, 1 sync per chunk.
// ---------------------------------------------------------------------------
#define KC 32
#define NC (C_DIM / KC)          // 32 chunks
#define KPAD 40                  // bf16 elems per smem row (80 bytes)
#define ROWB (KPAD * 2)          // 80 bytes
#define A_BYTES (64 * ROWB)      // 5120
#define B_BYTES (128 * ROWB)     // 10240
#define OFF_AH 0
#define OFF_AL (A_BYTES)
#define OFF_BH (2 * A_BYTES)
#define OFF_BL (2 * A_BYTES + B_BYTES)
#define STAGE_BYTES (2 * A_BYTES + 2 * B_BYTES)   // 30720
#define GEMM_SMEM (2 * STAGE_BYTES)               // 61440

__device__ __forceinline__ void mma_bf16(float* c, const uint32_t* a, const uint32_t* b) {
    asm volatile(
        "mma.sync.aligned.m16n8k16.row.col.f32.bf16.bf16.f32 "
        "{%0,%1,%2,%3}, {%4,%5,%6,%7}, {%8,%9}, {%0,%1,%2,%3};"
        : "+f"(c[0]), "+f"(c[1]), "+f"(c[2]), "+f"(c[3])
        : "r"(a[0]), "r"(a[1]), "r"(a[2]), "r"(a[3]), "r"(b[0]), "r"(b[1]));
}

__device__ __forceinline__ void split_store(char* hip, char* lop, float4 v) {
    __nv_bfloat162 h01 = __floats2bfloat162_rn(v.x, v.y);
    __nv_bfloat162 h23 = __floats2bfloat162_rn(v.z, v.w);
    __nv_bfloat162 l01 = __floats2bfloat162_rn(v.x - __bfloat162float(h01.x),
                                               v.y - __bfloat162float(h01.y));
    __nv_bfloat162 l23 = __floats2bfloat162_rn(v.z - __bfloat162float(h23.x),
                                               v.w - __bfloat162float(h23.y));
    *reinterpret_cast<uint2*>(hip) = make_uint2(bf2u(h01), bf2u(h23));
    *reinterpret_cast<uint2*>(lop) = make_uint2(bf2u(l01), bf2u(l23));
}

__global__ __launch_bounds__(256) void gates_gemm_mma(
    const float* __restrict__ emb, int rowOff,
    const float* __restrict__ Wk,  const float* __restrict__ bk,
    const float* __restrict__ Wb,  const float* __restrict__ bb,
    const float* __restrict__ Wg,  const float* __restrict__ bg,
    const float* __restrict__ Ws,  const float* __restrict__ bs,
    const float* __restrict__ Wgm, const float* __restrict__ bgm,
    const float* __restrict__ We,  const float* __restrict__ be,
    const float* __restrict__ Wa,  const float* __restrict__ ba)
{
    extern __shared__ __align__(16) char smem[];
    __shared__ float sBias[128];

    const int tid  = threadIdx.x;
    const int wid  = tid >> 5;
    const int lane = tid & 31;
    const int wm   = wid & 1;       // 0..1  (m: 32 rows each)
    const int wn   = wid >> 1;      // 0..3  (n: 32 cols each)
    const int rowBase = rowOff + blockIdx.x * 64;
    const int colBase = blockIdx.y * 128;

    if (tid < 128)
        sBias[tid] = bias_val(colBase + tid, bk, bb, bg, bs, bgm, be, ba);

    // hoisted W row pointers for the 4 B-load slots of this thread
    const float* bsrc[4];
#pragma unroll
    for (int t = 0; t < 4; ++t)
        bsrc[t] = wrow_ptr(colBase + ((t * 256 + tid) >> 3),
                           Wk, Wb, Wg, Ws, Wgm, We, Wa);

    float acc[2][4][4];
#pragma unroll
    for (int mt = 0; mt < 2; ++mt)
#pragma unroll
        for (int nt = 0; nt < 4; ++nt)
#pragma unroll
            for (int i = 0; i < 4; ++i) acc[mt][nt][i] = 0.f;

    float4 apf[2];
    float4 bpf[4];

    auto g2r = [&](int c) {
        const int k0 = c * KC;
#pragma unroll
        for (int t = 0; t < 2; ++t) {        // A: 64 rows x 8 float4
            const int i4  = t * 256 + tid;   // 0..511
            const int row = i4 >> 3;
            const int kq  = i4 & 7;
            apf[t] = *reinterpret_cast<const float4*>(
                emb + (size_t)(rowBase + row) * C_DIM + k0 + kq * 4);
        }
#pragma unroll
        for (int t = 0; t < 4; ++t) {        // B: 128 rows x 8 float4 (fp32 W)
            const int q = (t * 256 + tid) & 7;
            bpf[t] = bsrc[t]
                ? *reinterpret_cast<const float4*>(bsrc[t] + k0 + q * 4)
                : make_float4(0.f, 0.f, 0.f, 0.f);
        }
    };
    auto r2s = [&](int s) {
        char* st = smem + s * STAGE_BYTES;
#pragma unroll
        for (int t = 0; t < 2; ++t) {
            const int i4  = t * 256 + tid;
            const int row = i4 >> 3;
            const int kq  = i4 & 7;
            split_store(st + OFF_AH + row * ROWB + kq * 8,
                        st + OFF_AL + row * ROWB + kq * 8, apf[t]);
        }
#pragma unroll
        for (int t = 0; t < 4; ++t) {
            const int i   = t * 256 + tid;
            const int row = i >> 3;
            const int q   = i & 7;
            split_store(st + OFF_BH + row * ROWB + q * 8,
                        st + OFF_BL + row * ROWB + q * 8, bpf[t]);
        }
    };

    g2r(0);
    r2s(0);
    __syncthreads();

    const int ar = lane >> 2;          // 0..7
    const int ac = (lane & 3) * 2;     // 0,2,4,6

    for (int c = 0; c < NC; ++c) {
        if (c + 1 < NC) g2r(c + 1);    // gmem loads in flight during compute

        char* st = smem + (c & 1) * STAGE_BYTES;
#pragma unroll
        for (int kk = 0; kk < KC; kk += 16) {
            uint32_t ah[2][4], al[2][4], bh[4][2], bl[4][2];
            const int c0 = (kk + ac) * 2;
#pragma unroll
            for (int mt = 0; mt < 2; ++mt) {
                const int r0 = (wm * 32 + mt * 16 + ar) * ROWB;
                const int r8 = r0 + 8 * ROWB;
                ah[mt][0] = *reinterpret_cast<const uint32_t*>(st + OFF_AH + r0 + c0);
                ah[mt][1] = *reinterpret_cast<const uint32_t*>(st + OFF_AH + r8 + c0);
                ah[mt][2] = *reinterpret_cast<const uint32_t*>(st + OFF_AH + r0 + c0 + 16);
                ah[mt][3] = *reinterpret_cast<const uint32_t*>(st + OFF_AH + r8 + c0 + 16);
                al[mt][0] = *reinterpret_cast<const uint32_t*>(st + OFF_AL + r0 + c0);
                al[mt][1] = *reinterpret_cast<const uint32_t*>(st + OFF_AL + r8 + c0);
                al[mt][2] = *reinterpret_cast<const uint32_t*>(st + OFF_AL + r0 + c0 + 16);
                al[mt][3] = *reinterpret_cast<const uint32_t*>(st + OFF_AL + r8 + c0 + 16);
            }
#pragma unroll
            for (int nt = 0; nt < 4; ++nt) {
                const int rn = (wn * 32 + nt * 8 + ar) * ROWB;
                bh[nt][0] = *reinterpret_cast<const uint32_t*>(st + OFF_BH + rn + c0);
                bh[nt][1] = *reinterpret_cast<const uint32_t*>(st + OFF_BH + rn + c0 + 16);
                bl[nt][0] = *reinterpret_cast<const uint32_t*>(st + OFF_BL + rn + c0);
                bl[nt][1] = *reinterpret_cast<const uint32_t*>(st + OFF_BL + rn + c0 + 16);
            }
#pragma unroll
            for (int mt = 0; mt < 2; ++mt)
#pragma unroll
                for (int nt = 0; nt < 4; ++nt) {
                    mma_bf16(acc[mt][nt], ah[mt], bh[nt]);
                    mma_bf16(acc[mt][nt], ah[mt], bl[nt]);
                    mma_bf16(acc[mt][nt], al[mt], bh[nt]);
                }
        }

        if (c + 1 < NC) {
            r2s((c + 1) & 1);          // write other stage (safe: read 2 iters ago)
            __syncthreads();           // visibility for compute(c+1)
        }
    }

    // epilogue: D[row][col] layout of m16n8 f32 fragment
#pragma unroll
    for (int mt = 0; mt < 2; ++mt) {
        const int row0 = rowBase + wm * 32 + mt * 16 + (lane >> 2);
        float* g0 = g_G + (size_t)row0 * G_COLS;
        float* g1 = g_G + (size_t)(row0 + 8) * G_COLS;
#pragma unroll
        for (int nt = 0; nt < 4; ++nt) {
            const int lc  = wn * 32 + nt * 8 + (lane & 3) * 2;
            const int col = colBase + lc;
            if (col < G_COLS) {
                g0[col] = acc[mt][nt][0] + sBias[lc];
                g1[col] = acc[mt][nt][2] + sBias[lc];
            }
            if (col + 1 < G_COLS) {
                g0[col + 1] = acc[mt][nt][1] + sBias[lc + 1];
                g1[col + 1] = acc[mt][nt][3] + sBias[lc + 1];
            }
        }
    }
}

// ---------------------------------------------------------------------------
// Kernel 2: fused NTM write head (R14-proven). One CTA (256 thr) per batch
// row; two-pass streaming with 2-deep register prefetch in both phases.
//   i4 = ii*256 + tid  ->  n = ii*16 + (tid>>4),  m0 = (tid&15)*4
// ---------------------------------------------------------------------------
__global__ __launch_bounds__(256, 3) void write_head_kernel(
    int bOff,
    const float* __restrict__ w_prev,
    const float* __restrict__ memory,
    float* __restrict__ out_w,
    float* __restrict__ out_mem)
{
    __shared__ float sK[64], sE[64], sA[64];
    __shared__ float sDot[256], sNsq[256];
    __shared__ float sWg[256], sW[256];
    __shared__ float sRed[8], sRed2[8];
    __shared__ float sKred[2];
    __shared__ float sScal[8];             // beta,g,s0..s2,gamma

    const int b = bOff + blockIdx.x;
    const int tid = threadIdx.x;
    const int widx = tid >> 5;
    const int m0 = (tid & 15) * 4;

    // issue first two pipeline loads BEFORE gate processing (overlap)
    const float4* memv = (const float4*)(memory + (size_t)b * (N_DIM * M_DIM));
    float4 pf0 = memv[tid];
    float4 pf1 = memv[256 + tid];

    const float* Grow = g_G + (size_t)b * G_COLS;
    if (tid < 64) {
        float kv = Grow[tid];
        sK[tid] = kv;
        sE[tid] = sigmoid_f(Grow[70 + tid]);
        sA[tid] = Grow[134 + tid];
        float kk = kv * kv;
#pragma unroll
        for (int o = 16; o > 0; o >>= 1) kk += __shfl_xor_sync(0xffffffffu, kk, o);
        if ((tid & 31) == 0) sKred[tid >> 5] = kk;
    } else if (tid == 64) {
        sScal[0] = softplus_f(Grow[64]);            // beta
    } else if (tid == 65) {
        sScal[1] = sigmoid_f(Grow[65]);             // g
    } else if (tid == 66) {
        sScal[5] = 1.f + softplus_f(Grow[69]);      // gamma
    } else if (tid == 67) {
        float x0 = Grow[66], x1 = Grow[67], x2 = Grow[68];
        float mx = fmaxf(x0, fmaxf(x1, x2));
        float e0 = expf(x0 - mx), e1 = expf(x1 - mx), e2 = expf(x2 - mx);
        float inv = 1.f / (e0 + e1 + e2);
        sScal[2] = e0 * inv; sScal[3] = e1 * inv; sScal[4] = e2 * inv;
    }
    const float wp = w_prev[(size_t)b * N_DIM + tid];
    __syncthreads();                       // sK visible

    // phase 1: stream memory row (pipelined), accumulate dot(k)/norm^2
    {
        const float k0 = sK[m0], k1 = sK[m0 + 1], k2 = sK[m0 + 2], k3 = sK[m0 + 3];
        float4 cur = pf0, nxt = pf1;
#pragma unroll
        for (int ii = 0; ii < 16; ++ii) {
            float4 pre;
            if (ii + 2 < 16) pre = memv[(ii + 2) * 256 + tid];
            float d = cur.x * k0 + cur.y * k1 + cur.z * k2 + cur.w * k3;
            float q = cur.x * cur.x + cur.y * cur.y + cur.z * cur.z + cur.w * cur.w;
#pragma unroll
            for (int o = 8; o > 0; o >>= 1) {
                d += __shfl_xor_sync(0xffffffffu, d, o);
                q += __shfl_xor_sync(0xffffffffu, q, o);
            }
            if ((tid & 15) == 0) {
                const int n = ii * 16 + (tid >> 4);
                sDot[n] = d;
                sNsq[n] = q;
            }
            cur = nxt;
            nxt = pre;
        }
    }
    __syncthreads();

    const float knorm = __fsqrt_rn(sKred[0] + sKred[1]);
    const float beta  = sScal[0];
    const float g     = sScal[1];
    const float s0    = sScal[2], s1 = sScal[3], s2 = sScal[4];
    const float gamma = sScal[5];

    // phase 2: softmax chain (no max subtraction; logits bounded by |beta|)
    const int n = tid;
    float cosv = sDot[n] / (fmaxf(__fsqrt_rn(sNsq[n]), 1e-8f) * fmaxf(knorm, 1e-8f));
    float ex = __expf(beta * cosv);

    float sv = ex;
#pragma unroll
    for (int o = 16; o > 0; o >>= 1) sv += __shfl_xor_sync(0xffffffffu, sv, o);
    if ((tid & 31) == 0) sRed[widx] = sv;
    __syncthreads();
    float sum = sRed[0] + sRed[1] + sRed[2] + sRed[3]
              + sRed[4] + sRed[5] + sRed[6] + sRed[7];

    float wc = ex / sum;
    float wg = g * wc + (1.f - g) * wp;
    sWg[n] = wg;
    __syncthreads();

    float wsh = s0 * sWg[(n + 255) & 255] + s1 * wg + s2 * sWg[(n + 1) & 255];
    float wpow = __powf(wsh, gamma);
    float pv = wpow;
#pragma unroll
    for (int o = 16; o > 0; o >>= 1) pv += __shfl_xor_sync(0xffffffffu, pv, o);
    if ((tid & 31) == 0) sRed2[widx] = pv;
    __syncthreads();
    float psum = sRed2[0] + sRed2[1] + sRed2[2] + sRed2[3]
               + sRed2[4] + sRed2[5] + sRed2[6] + sRed2[7];

    float wfin = wpow / (psum + 1e-16f);
    out_w[(size_t)b * N_DIM + n] = wfin;
    sW[n] = wfin;

    // prefetch phase-3 first loads before the barrier (pure gmem, no dep)
    float4 q0 = __ldcs(memv + tid);
    float4 q1 = __ldcs(memv + 256 + tid);
    __syncthreads();

    // phase 3: re-read row (pipelined, last-use) and stream the update out
    {
        const float4 e4 = *reinterpret_cast<const float4*>(sE + m0);
        const float4 a4 = *reinterpret_cast<const float4*>(sA + m0);
        float4* outv = (float4*)(out_mem + (size_t)b * (N_DIM * M_DIM));
        float4 cur = q0, nxt = q1;
#pragma unroll
        for (int ii = 0; ii < 16; ++ii) {
            float4 pre;
            if (ii + 2 < 16) pre = __ldcs(memv + (ii + 2) * 256 + tid);
            const float wn = sW[ii * 16 + (tid >> 4)];
            float4 r;
            r.x = cur.x * (1.f - wn * e4.x) + wn * a4.x;
            r.y = cur.y * (1.f - wn * e4.y) + wn * a4.y;
            r.z = cur.z * (1.f - wn * e4.z) + wn * a4.z;
            r.w = cur.w * (1.f - wn * e4.w) + wn * a4.w;
            __stcs(outv + ii * 256 + tid, r);
            cur = nxt;
            nxt = pre;
        }
    }
}

// ---------------------------------------------------------------------------
// Launch: 2-chunk cross-stream pipeline.
//   capture stream: gemm(half0) -> evA -> gemm(half1) -> evB
//   side stream:    wait(evA) -> head(half0) -> wait(evB) -> head(half1)
//   join:           evJ on side stream; capture stream waits evJ
// gemm(half1) is hidden under head(half0)'s DRAM stream.
// ---------------------------------------------------------------------------
extern "C" void kernel_launch(void* const* d_in, const int* in_sizes, int n_in,
                              void* d_out, int out_size)
{
    const float* emb    = (const float*)d_in[0];
    const float* w_prev = (const float*)d_in[1];
    const float* memory = (const float*)d_in[2];
    const float* Wk  = (const float*)d_in[3];  const float* bk  = (const float*)d_in[4];
    const float* Wb  = (const float*)d_in[5];  const float* bb  = (const float*)d_in[6];
    const float* Wg  = (const float*)d_in[7];  const float* bg  = (const float*)d_in[8];
    const float* Ws  = (const float*)d_in[9];  const float* bs  = (const float*)d_in[10];
    const float* Wgm = (const float*)d_in[11]; const float* bgm = (const float*)d_in[12];
    const float* We  = (const float*)d_in[13]; const float* be  = (const float*)d_in[14];
    const float* Wa  = (const float*)d_in[15]; const float* ba  = (const float*)d_in[16];

    float* out_w   = (float*)d_out;                       // [B, N]
    float* out_mem = out_w + (size_t)B_SZ * N_DIM;        // [B, N, M]

    static cudaStream_t sSide = nullptr;
    static cudaEvent_t evA = nullptr, evB = nullptr, evJ = nullptr;
    if (sSide == nullptr) {
        cudaStreamCreateWithFlags(&sSide, cudaStreamNonBlocking);
        cudaEventCreateWithFlags(&evA, cudaEventDisableTiming);
        cudaEventCreateWithFlags(&evB, cudaEventDisableTiming);
        cudaEventCreateWithFlags(&evJ, cudaEventDisableTiming);
        cudaFuncSetAttribute(gates_gemm_mma,
                             cudaFuncAttributeMaxDynamicSharedMemorySize, GEMM_SMEM);
    }

    gates_gemm_mma<<<dim3(HALF_B / 64, 2), 256, GEMM_SMEM>>>(
        emb, 0, Wk, bk, Wb, bb, Wg, bg, Ws, bs, Wgm, bgm, We, be, Wa, ba);
    cudaEventRecord(evA, 0);
    gates_gemm_mma<<<dim3(HALF_B / 64, 2), 256, GEMM_SMEM>>>(
        emb, HALF_B, Wk, bk, Wb, bb, Wg, bg, Ws, bs, Wgm, bgm, We, be, Wa, ba);
    cudaEventRecord(evB, 0);

    cudaStreamWaitEvent(sSide, evA, 0);
    write_head_kernel<<<HALF_B, 256, 0, sSide>>>(0, w_prev, memory, out_w, out_mem);
    cudaStreamWaitEvent(sSide, evB, 0);
    write_head_kernel<<<HALF_B, 256, 0, sSide>>>(HALF_B, w_prev, memory, out_w, out_mem);
    cudaEventRecord(evJ, sSide);
    cudaStreamWaitEvent(0, evJ, 0);
}

// round 16
// speedup vs baseline: 1.1762x; 1.1762x over previous
#include <cuda_runtime.h>
#include <cuda_bf16.h>
#include <math.h>
#include <stdint.h>

#define B_SZ   4096
#define C_DIM  1024
#define N_DIM  256
#define M_DIM  64
#define G_COLS 198

// ---------------------------------------------------------------------------
// device scratch
// ---------------------------------------------------------------------------
__device__ float g_G[B_SZ * G_COLS];                 // gate pre-activations

__device__ __forceinline__ float softplus_f(float x) {
    return (x > 20.f) ? x : log1pf(expf(x));
}
__device__ __forceinline__ float sigmoid_f(float x) {
    return 1.f / (1.f + expf(-x));
}
__device__ __forceinline__ uint32_t bf2u(__nv_bfloat162 v) {
    return *reinterpret_cast<uint32_t*>(&v);
}

// row c of the concatenated weight matrix [198, 1024]
__device__ __forceinline__ const float* wrow_ptr(
    int c, const float* Wk, const float* Wb, const float* Wg,
    const float* Ws, const float* Wgm, const float* We, const float* Wa)
{
    if (c < 64)   return Wk + (size_t)c * C_DIM;
    if (c == 64)  return Wb;
    if (c == 65)  return Wg;
    if (c < 69)   return Ws + (size_t)(c - 66) * C_DIM;
    if (c == 69)  return Wgm;
    if (c < 134)  return We + (size_t)(c - 70) * C_DIM;
    if (c < 198)  return Wa + (size_t)(c - 134) * C_DIM;
    return nullptr;
}
__device__ __forceinline__ float bias_val(
    int c, const float* bk, const float* bb, const float* bg,
    const float* bs, const float* bgm, const float* be, const float* ba)
{
    if (c < 64)   return bk[c];
    if (c == 64)  return bb[0];
    if (c == 65)  return bg[0];
    if (c < 69)   return bs[c - 66];
    if (c == 69)  return bgm[0];
    if (c < 134)  return be[c - 70];
    if (c < 198)  return ba[c - 134];
    return 0.f;
}

// ---------------------------------------------------------------------------
// Kernel 1: HMMA bf16-split GEMM  G[4096,198] = emb @ Wcat.T + b
// Folded W conversion. CTA tile 64x64 (was 64x128) -> grid (64,4)=256 CTAs,
// stage smem 20KB (40KB double-buffered) -> 2+ CTAs/SM for latency hiding.
// 8 warps (2m x 4n), warp tile 32x16. K-chunk 32 fp32:
// {Ahi*Bhi + Ahi*Blo + Alo*Bhi}. Register-prefetch G2R, 1 sync per chunk.
// ---------------------------------------------------------------------------
#define KC 32
#define NC (C_DIM / KC)          // 32 chunks
#define KPAD 40                  // bf16 elems per smem row (80 bytes)
#define ROWB (KPAD * 2)          // 80 bytes
#define A_BYTES (64 * ROWB)      // 5120
#define B_BYTES (64 * ROWB)      // 5120
#define OFF_AH 0
#define OFF_AL (A_BYTES)
#define OFF_BH (2 * A_BYTES)
#define OFF_BL (2 * A_BYTES + B_BYTES)
#define STAGE_BYTES (2 * A_BYTES + 2 * B_BYTES)   // 20480
#define GEMM_SMEM (2 * STAGE_BYTES)               // 40960

__device__ __forceinline__ void mma_bf16(float* c, const uint32_t* a, const uint32_t* b) {
    asm volatile(
        "mma.sync.aligned.m16n8k16.row.col.f32.bf16.bf16.f32 "
        "{%0,%1,%2,%3}, {%4,%5,%6,%7}, {%8,%9}, {%0,%1,%2,%3};"
        : "+f"(c[0]), "+f"(c[1]), "+f"(c[2]), "+f"(c[3])
        : "r"(a[0]), "r"(a[1]), "r"(a[2]), "r"(a[3]), "r"(b[0]), "r"(b[1]));
}

__device__ __forceinline__ void split_store(char* hip, char* lop, float4 v) {
    __nv_bfloat162 h01 = __floats2bfloat162_rn(v.x, v.y);
    __nv_bfloat162 h23 = __floats2bfloat162_rn(v.z, v.w);
    __nv_bfloat162 l01 = __floats2bfloat162_rn(v.x - __bfloat162float(h01.x),
                                               v.y - __bfloat162float(h01.y));
    __nv_bfloat162 l23 = __floats2bfloat162_rn(v.z - __bfloat162float(h23.x),
                                               v.w - __bfloat162float(h23.y));
    *reinterpret_cast<uint2*>(hip) = make_uint2(bf2u(h01), bf2u(h23));
    *reinterpret_cast<uint2*>(lop) = make_uint2(bf2u(l01), bf2u(l23));
}

__global__ __launch_bounds__(256) void gates_gemm_mma(
    const float* __restrict__ emb,
    const float* __restrict__ Wk,  const float* __restrict__ bk,
    const float* __restrict__ Wb,  const float* __restrict__ bb,
    const float* __restrict__ Wg,  const float* __restrict__ bg,
    const float* __restrict__ Ws,  const float* __restrict__ bs,
    const float* __restrict__ Wgm, const float* __restrict__ bgm,
    const float* __restrict__ We,  const float* __restrict__ be,
    const float* __restrict__ Wa,  const float* __restrict__ ba)
{
    extern __shared__ __align__(16) char smem[];
    __shared__ float sBias[64];

    const int tid  = threadIdx.x;
    const int wid  = tid >> 5;
    const int lane = tid & 31;
    const int wm   = wid & 1;       // 0..1  (m: 32 rows each)
    const int wn   = wid >> 1;      // 0..3  (n: 16 cols each)
    const int rowBase = blockIdx.x * 64;
    const int colBase = blockIdx.y * 64;

    if (tid < 64)
        sBias[tid] = bias_val(colBase + tid, bk, bb, bg, bs, bgm, be, ba);

    // hoisted W row pointers for the 2 B-load slots of this thread
    const float* bsrc[2];
#pragma unroll
    for (int t = 0; t < 2; ++t)
        bsrc[t] = wrow_ptr(colBase + ((t * 256 + tid) >> 3),
                           Wk, Wb, Wg, Ws, Wgm, We, Wa);

    float acc[2][2][4];
#pragma unroll
    for (int mt = 0; mt < 2; ++mt)
#pragma unroll
        for (int nt = 0; nt < 2; ++nt)
#pragma unroll
            for (int i = 0; i < 4; ++i) acc[mt][nt][i] = 0.f;

    float4 apf[2];
    float4 bpf[2];

    auto g2r = [&](int c) {
        const int k0 = c * KC;
#pragma unroll
        for (int t = 0; t < 2; ++t) {        // A: 64 rows x 8 float4
            const int i4  = t * 256 + tid;   // 0..511
            const int row = i4 >> 3;
            const int kq  = i4 & 7;
            apf[t] = *reinterpret_cast<const float4*>(
                emb + (size_t)(rowBase + row) * C_DIM + k0 + kq * 4);
        }
#pragma unroll
        for (int t = 0; t < 2; ++t) {        // B: 64 rows x 8 float4 (fp32 W)
            const int q = (t * 256 + tid) & 7;
            bpf[t] = bsrc[t]
                ? *reinterpret_cast<const float4*>(bsrc[t] + k0 + q * 4)
                : make_float4(0.f, 0.f, 0.f, 0.f);
        }
    };
    auto r2s = [&](int s) {
        char* st = smem + s * STAGE_BYTES;
#pragma unroll
        for (int t = 0; t < 2; ++t) {
            const int i4  = t * 256 + tid;
            const int row = i4 >> 3;
            const int kq  = i4 & 7;
            split_store(st + OFF_AH + row * ROWB + kq * 8,
                        st + OFF_AL + row * ROWB + kq * 8, apf[t]);
        }
#pragma unroll
        for (int t = 0; t < 2; ++t) {
            const int i   = t * 256 + tid;
            const int row = i >> 3;
            const int q   = i & 7;
            split_store(st + OFF_BH + row * ROWB + q * 8,
                        st + OFF_BL + row * ROWB + q * 8, bpf[t]);
        }
    };

    g2r(0);
    r2s(0);
    __syncthreads();

    const int ar = lane >> 2;          // 0..7
    const int ac = (lane & 3) * 2;     // 0,2,4,6

    for (int c = 0; c < NC; ++c) {
        if (c + 1 < NC) g2r(c + 1);    // gmem loads in flight during compute

        char* st = smem + (c & 1) * STAGE_BYTES;
#pragma unroll
        for (int kk = 0; kk < KC; kk += 16) {
            uint32_t ah[2][4], al[2][4], bh[2][2], bl[2][2];
            const int c0 = (kk + ac) * 2;
#pragma unroll
            for (int mt = 0; mt < 2; ++mt) {
                const int r0 = (wm * 32 + mt * 16 + ar) * ROWB;
                const int r8 = r0 + 8 * ROWB;
                ah[mt][0] = *reinterpret_cast<const uint32_t*>(st + OFF_AH + r0 + c0);
                ah[mt][1] = *reinterpret_cast<const uint32_t*>(st + OFF_AH + r8 + c0);
                ah[mt][2] = *reinterpret_cast<const uint32_t*>(st + OFF_AH + r0 + c0 + 16);
                ah[mt][3] = *reinterpret_cast<const uint32_t*>(st + OFF_AH + r8 + c0 + 16);
                al[mt][0] = *reinterpret_cast<const uint32_t*>(st + OFF_AL + r0 + c0);
                al[mt][1] = *reinterpret_cast<const uint32_t*>(st + OFF_AL + r8 + c0);
                al[mt][2] = *reinterpret_cast<const uint32_t*>(st + OFF_AL + r0 + c0 + 16);
                al[mt][3] = *reinterpret_cast<const uint32_t*>(st + OFF_AL + r8 + c0 + 16);
            }
#pragma unroll
            for (int nt = 0; nt < 2; ++nt) {
                const int rn = (wn * 16 + nt * 8 + ar) * ROWB;
                bh[nt][0] = *reinterpret_cast<const uint32_t*>(st + OFF_BH + rn + c0);
                bh[nt][1] = *reinterpret_cast<const uint32_t*>(st + OFF_BH + rn + c0 + 16);
                bl[nt][0] = *reinterpret_cast<const uint32_t*>(st + OFF_BL + rn + c0);
                bl[nt][1] = *reinterpret_cast<const uint32_t*>(st + OFF_BL + rn + c0 + 16);
            }
#pragma unroll
            for (int mt = 0; mt < 2; ++mt)
#pragma unroll
                for (int nt = 0; nt < 2; ++nt) {
                    mma_bf16(acc[mt][nt], ah[mt], bh[nt]);
                    mma_bf16(acc[mt][nt], ah[mt], bl[nt]);
                    mma_bf16(acc[mt][nt], al[mt], bh[nt]);
                }
        }

        if (c + 1 < NC) {
            r2s((c + 1) & 1);          // write other stage (safe: read 2 iters ago)
            __syncthreads();           // visibility for compute(c+1)
        }
    }

    // epilogue: D[row][col] layout of m16n8 f32 fragment
#pragma unroll
    for (int mt = 0; mt < 2; ++mt) {
        const int row0 = rowBase + wm * 32 + mt * 16 + (lane >> 2);
        float* g0 = g_G + (size_t)row0 * G_COLS;
        float* g1 = g_G + (size_t)(row0 + 8) * G_COLS;
#pragma unroll
        for (int nt = 0; nt < 2; ++nt) {
            const int lc  = wn * 16 + nt * 8 + (lane & 3) * 2;
            const int col = colBase + lc;
            if (col < G_COLS) {
                g0[col] = acc[mt][nt][0] + sBias[lc];
                g1[col] = acc[mt][nt][2] + sBias[lc];
            }
            if (col + 1 < G_COLS) {
                g0[col + 1] = acc[mt][nt][1] + sBias[lc + 1];
                g1[col + 1] = acc[mt][nt][3] + sBias[lc + 1];
            }
        }
    }
}

// ---------------------------------------------------------------------------
// Kernel 2: fused NTM write head (R14-proven, unchanged). One CTA (256 thr)
// per batch row; two-pass streaming with 2-deep register prefetch.
//   i4 = ii*256 + tid  ->  n = ii*16 + (tid>>4),  m0 = (tid&15)*4
// ---------------------------------------------------------------------------
__global__ __launch_bounds__(256, 3) void write_head_kernel(
    const float* __restrict__ w_prev,
    const float* __restrict__ memory,
    float* __restrict__ out_w,
    float* __restrict__ out_mem)
{
    __shared__ float sK[64], sE[64], sA[64];
    __shared__ float sDot[256], sNsq[256];
    __shared__ float sWg[256], sW[256];
    __shared__ float sRed[8], sRed2[8];
    __shared__ float sKred[2];
    __shared__ float sScal[8];             // beta,g,s0..s2,gamma

    const int b = blockIdx.x;
    const int tid = threadIdx.x;
    const int widx = tid >> 5;
    const int m0 = (tid & 15) * 4;

    // issue first two pipeline loads BEFORE gate processing (overlap)
    const float4* memv = (const float4*)(memory + (size_t)b * (N_DIM * M_DIM));
    float4 pf0 = memv[tid];
    float4 pf1 = memv[256 + tid];

    const float* Grow = g_G + (size_t)b * G_COLS;
    if (tid < 64) {
        float kv = Grow[tid];
        sK[tid] = kv;
        sE[tid] = sigmoid_f(Grow[70 + tid]);
        sA[tid] = Grow[134 + tid];
        float kk = kv * kv;
#pragma unroll
        for (int o = 16; o > 0; o >>= 1) kk += __shfl_xor_sync(0xffffffffu, kk, o);
        if ((tid & 31) == 0) sKred[tid >> 5] = kk;
    } else if (tid == 64) {
        sScal[0] = softplus_f(Grow[64]);            // beta
    } else if (tid == 65) {
        sScal[1] = sigmoid_f(Grow[65]);             // g
    } else if (tid == 66) {
        sScal[5] = 1.f + softplus_f(Grow[69]);      // gamma
    } else if (tid == 67) {
        float x0 = Grow[66], x1 = Grow[67], x2 = Grow[68];
        float mx = fmaxf(x0, fmaxf(x1, x2));
        float e0 = expf(x0 - mx), e1 = expf(x1 - mx), e2 = expf(x2 - mx);
        float inv = 1.f / (e0 + e1 + e2);
        sScal[2] = e0 * inv; sScal[3] = e1 * inv; sScal[4] = e2 * inv;
    }
    const float wp = w_prev[(size_t)b * N_DIM + tid];
    __syncthreads();                       // sK visible

    // phase 1: stream memory row (pipelined), accumulate dot(k)/norm^2
    {
        const float k0 = sK[m0], k1 = sK[m0 + 1], k2 = sK[m0 + 2], k3 = sK[m0 + 3];
        float4 cur = pf0, nxt = pf1;
#pragma unroll
        for (int ii = 0; ii < 16; ++ii) {
            float4 pre;
            if (ii + 2 < 16) pre = memv[(ii + 2) * 256 + tid];
            float d = cur.x * k0 + cur.y * k1 + cur.z * k2 + cur.w * k3;
            float q = cur.x * cur.x + cur.y * cur.y + cur.z * cur.z + cur.w * cur.w;
#pragma unroll
            for (int o = 8; o > 0; o >>= 1) {
                d += __shfl_xor_sync(0xffffffffu, d, o);
                q += __shfl_xor_sync(0xffffffffu, q, o);
            }
            if ((tid & 15) == 0) {
                const int n = ii * 16 + (tid >> 4);
                sDot[n] = d;
                sNsq[n] = q;
            }
            cur = nxt;
            nxt = pre;
        }
    }
    __syncthreads();

    const float knorm = __fsqrt_rn(sKred[0] + sKred[1]);
    const float beta  = sScal[0];
    const float g     = sScal[1];
    const float s0    = sScal[2], s1 = sScal[3], s2 = sScal[4];
    const float gamma = sScal[5];

    // phase 2: softmax chain (no max subtraction; logits bounded by |beta|)
    const int n = tid;
    float cosv = sDot[n] / (fmaxf(__fsqrt_rn(sNsq[n]), 1e-8f) * fmaxf(knorm, 1e-8f));
    float ex = __expf(beta * cosv);

    float sv = ex;
#pragma unroll
    for (int o = 16; o > 0; o >>= 1) sv += __shfl_xor_sync(0xffffffffu, sv, o);
    if ((tid & 31) == 0) sRed[widx] = sv;
    __syncthreads();
    float sum = sRed[0] + sRed[1] + sRed[2] + sRed[3]
              + sRed[4] + sRed[5] + sRed[6] + sRed[7];

    float wc = ex / sum;
    float wg = g * wc + (1.f - g) * wp;
    sWg[n] = wg;
    __syncthreads();

    float wsh = s0 * sWg[(n + 255) & 255] + s1 * wg + s2 * sWg[(n + 1) & 255];
    float wpow = __powf(wsh, gamma);
    float pv = wpow;
#pragma unroll
    for (int o = 16; o > 0; o >>= 1) pv += __shfl_xor_sync(0xffffffffu, pv, o);
    if ((tid & 31) == 0) sRed2[widx] = pv;
    __syncthreads();
    float psum = sRed2[0] + sRed2[1] + sRed2[2] + sRed2[3]
               + sRed2[4] + sRed2[5] + sRed2[6] + sRed2[7];

    float wfin = wpow / (psum + 1e-16f);
    out_w[(size_t)b * N_DIM + n] = wfin;
    sW[n] = wfin;

    // prefetch phase-3 first loads before the barrier (pure gmem, no dep)
    float4 q0 = __ldcs(memv + tid);
    float4 q1 = __ldcs(memv + 256 + tid);
    __syncthreads();

    // phase 3: re-read row (pipelined, last-use) and stream the update out
    {
        const float4 e4 = *reinterpret_cast<const float4*>(sE + m0);
        const float4 a4 = *reinterpret_cast<const float4*>(sA + m0);
        float4* outv = (float4*)(out_mem + (size_t)b * (N_DIM * M_DIM));
        float4 cur = q0, nxt = q1;
#pragma unroll
        for (int ii = 0; ii < 16; ++ii) {
            float4 pre;
            if (ii + 2 < 16) pre = __ldcs(memv + (ii + 2) * 256 + tid);
            const float wn = sW[ii * 16 + (tid >> 4)];
            float4 r;
            r.x = cur.x * (1.f - wn * e4.x) + wn * a4.x;
            r.y = cur.y * (1.f - wn * e4.y) + wn * a4.y;
            r.z = cur.z * (1.f - wn * e4.z) + wn * a4.z;
            r.w = cur.w * (1.f - wn * e4.w) + wn * a4.w;
            __stcs(outv + ii * 256 + tid, r);
            cur = nxt;
            nxt = pre;
        }
    }
}

// ---------------------------------------------------------------------------
extern "C" void kernel_launch(void* const* d_in, const int* in_sizes, int n_in,
                              void* d_out, int out_size)
{
    const float* emb    = (const float*)d_in[0];
    const float* w_prev = (const float*)d_in[1];
    const float* memory = (const float*)d_in[2];
    const float* Wk  = (const float*)d_in[3];  const float* bk  = (const float*)d_in[4];
    const float* Wb  = (const float*)d_in[5];  const float* bb  = (const float*)d_in[6];
    const float* Wg  = (const float*)d_in[7];  const float* bg  = (const float*)d_in[8];
    const float* Ws  = (const float*)d_in[9];  const float* bs  = (const float*)d_in[10];
    const float* Wgm = (const float*)d_in[11]; const float* bgm = (const float*)d_in[12];
    const float* We  = (const float*)d_in[13]; const float* be  = (const float*)d_in[14];
    const float* Wa  = (const float*)d_in[15]; const float* ba  = (const float*)d_in[16];

    float* out_w   = (float*)d_out;                       // [B, N]
    float* out_mem = out_w + (size_t)B_SZ * N_DIM;        // [B, N, M]

    cudaFuncSetAttribute(gates_gemm_mma,
                         cudaFuncAttributeMaxDynamicSharedMemorySize, GEMM_SMEM);

    gates_gemm_mma<<<dim3(B_SZ / 64, 4), 256, GEMM_SMEM>>>(
        emb, Wk, bk, Wb, bb, Wg, bg, Ws, bs, Wgm, bgm, We, be, Wa, ba);
    write_head_kernel<<<B_SZ, 256>>>(w_prev, memory, out_w, out_mem);
}